// round 1
// baseline (speedup 1.0000x reference)
#include <cuda_runtime.h>
#include <math.h>

#define D 32
#define HID 64
#define BATCH 2
#define NQ 512
#define NK 512
#define NROWS (BATCH*NQ + BATCH*NK)   // 2048
#define KD 1152                        // padded feature dim (528+528+32+32+2 -> 1152)

// Scratch (device globals: allocation-free rule)
__device__ float g_L [NROWS * 1024];          // 8 MB   lower-tri factors, row-major 32x32
__device__ float g_FQ[BATCH * NQ * KD];       // 4.5 MB feature rows for Q
__device__ float g_FK[BATCH * NK * KD];       // 4.5 MB feature rows for K

// ---------------------------------------------------------------------------
// Kernel A: per-row MLP -> raw -> L.   8 rows per block, 256 threads.
// ---------------------------------------------------------------------------
__global__ void __launch_bounds__(256) kA(
    const float* __restrict__ Q, const float* __restrict__ K,
    const float* __restrict__ w1, const float* __restrict__ b1,
    const float* __restrict__ w2, const float* __restrict__ b2)
{
    __shared__ float sx[8 * 32];
    __shared__ float sh[8 * HID];
    const int tid = threadIdx.x;
    const int rowBase = blockIdx.x * 8;

    // load 8 input rows (32 floats each)
    {
        int r = tid >> 5, c = tid & 31;
        int gr = rowBase + r;
        const float* src = (gr < BATCH * NQ) ? (Q + gr * D)
                                             : (K + (gr - BATCH * NQ) * D);
        sx[r * 32 + c] = src[c];
    }
    __syncthreads();

    // hidden: h = silu(x @ w1 + b1), 8*64 outputs
    for (int o = tid; o < 8 * HID; o += 256) {
        int r = o >> 6, h = o & 63;
        float acc = b1[h];
        #pragma unroll
        for (int k = 0; k < 32; k++)
            acc = fmaf(sx[r * 32 + k], w1[k * HID + h], acc);
        float s = 1.f / (1.f + expf(-acc));
        sh[r * HID + h] = acc * s;
    }
    __syncthreads();

    // raw = h @ w2 + b2 : each thread 4 consecutive out-cols x 8 rows
    const int c4 = tid * 4;
    float acc[8][4];
    #pragma unroll
    for (int r = 0; r < 8; r++) {
        acc[r][0] = b2[c4 + 0]; acc[r][1] = b2[c4 + 1];
        acc[r][2] = b2[c4 + 2]; acc[r][3] = b2[c4 + 3];
    }
    for (int k = 0; k < HID; k++) {
        float4 w = *reinterpret_cast<const float4*>(&w2[k * 1024 + c4]);
        #pragma unroll
        for (int r = 0; r < 8; r++) {
            float hv = sh[r * HID + k];
            acc[r][0] = fmaf(hv, w.x, acc[r][0]);
            acc[r][1] = fmaf(hv, w.y, acc[r][1]);
            acc[r][2] = fmaf(hv, w.z, acc[r][2]);
            acc[r][3] = fmaf(hv, w.w, acc[r][3]);
        }
    }

    // L construction: clamp, +I, tril, softplus diag
    #pragma unroll
    for (int r = 0; r < 8; r++) {
        int gr = rowBase + r;
        #pragma unroll
        for (int j = 0; j < 4; j++) {
            int e = c4 + j;
            int i = e >> 5, jj = e & 31;
            float t = 5.f * tanhf(acc[r][j] / 5.f);
            float Lv;
            if (jj > i) {
                Lv = 0.f;
            } else if (jj == i) {
                float z = t + 1.f;
                // stable softplus
                Lv = fmaxf(z, 0.f) + log1pf(expf(-fabsf(z))) + 1e-4f;
            } else {
                Lv = t;
            }
            g_L[gr * 1024 + e] = Lv;
        }
    }
}

// ---------------------------------------------------------------------------
// Kernel B: per-row G = L L^T, u = G x, a = x^T G x, emit feature row.
// One row per block, 256 threads.
// Feature layout (KD=1152):
//   FQ: [0..527]=packGq(dbl offdiag) [528..1055]=qq-pack [1056..]=u [1088..]=q
//       [1120]=a [1121]=1 [1122..]=0
//   FK: [0..527]=kk-pack [528..1055]=packGk(dbl) [1056..]=-2k [1088..]=-2w
//       [1120]=1 [1121]=c [1122..]=0
// ---------------------------------------------------------------------------
__global__ void __launch_bounds__(256) kB(
    const float* __restrict__ Q, const float* __restrict__ K)
{
    __shared__ float sL[1024];
    __shared__ float sG[1024];
    __shared__ float sx[32];
    __shared__ float su[32];
    __shared__ float sa;

    const int tid = threadIdx.x;
    const int gr = blockIdx.x;
    const bool qrow = (gr < BATCH * NQ);
    const float* src = qrow ? (Q + gr * D) : (K + (gr - BATCH * NQ) * D);

    #pragma unroll
    for (int t = tid; t < 1024; t += 256) sL[t] = g_L[gr * 1024 + t];
    if (tid < 32) sx[tid] = src[tid];
    __syncthreads();

    // G lower triangle (528 entries), mirrored to full matrix
    for (int e = tid; e < 528; e += 256) {
        int i = (int)((sqrtf(8.f * (float)e + 1.f) - 1.f) * 0.5f);
        while ((i + 1) * (i + 2) / 2 <= e) i++;
        while (i * (i + 1) / 2 > e) i--;
        int j = e - i * (i + 1) / 2;   // j <= i
        float s = 0.f;
        for (int t = 0; t <= j; t++)   // L is lower-tri: terms t<=min(i,j)=j
            s = fmaf(sL[i * 32 + t], sL[j * 32 + t], s);
        sG[i * 32 + j] = s;
        sG[j * 32 + i] = s;
    }
    __syncthreads();

    if (tid < 32) {
        float u = 0.f;
        #pragma unroll
        for (int j = 0; j < 32; j++)
            u = fmaf(sG[tid * 32 + j], sx[j], u);
        su[tid] = u;
    }
    __syncthreads();
    if (tid == 0) {
        float a = 0.f;
        #pragma unroll
        for (int i = 0; i < 32; i++) a = fmaf(su[i], sx[i], a);
        sa = a;
    }
    __syncthreads();

    float* F = qrow ? (g_FQ + gr * KD)
                    : (g_FK + (gr - BATCH * NQ) * KD);

    for (int e = tid; e < 528; e += 256) {
        int i = (int)((sqrtf(8.f * (float)e + 1.f) - 1.f) * 0.5f);
        while ((i + 1) * (i + 2) / 2 <= e) i++;
        while (i * (i + 1) / 2 > e) i--;
        int j = e - i * (i + 1) / 2;
        float g = sG[i * 32 + j];
        float packG = (i == j) ? g : 2.f * g;
        float xx = sx[i] * sx[j];
        F[e]       = qrow ? packG : xx;
        F[528 + e] = qrow ? xx : packG;
    }
    if (tid < 32) {
        F[1056 + tid] = qrow ? su[tid]       : -2.f * sx[tid];
        F[1088 + tid] = qrow ? sx[tid]       : -2.f * su[tid];
    }
    if (tid < 30) F[1122 + tid] = 0.f;
    if (tid == 0) {
        F[1120] = qrow ? sa  : 1.f;
        F[1121] = qrow ? 1.f : sa;
    }
}

// ---------------------------------------------------------------------------
// Kernel C: per batch  C[n][m] = sqrt(clip(0.5 * FQ[n] . FK[m]))
// NT-GEMM, 64x64 tile, 256 threads, 4x4 micro-tile, K chunk 32.
// ---------------------------------------------------------------------------
__global__ void __launch_bounds__(256) kC(float* __restrict__ out)
{
    __shared__ float As[64 * 33];
    __shared__ float Bs[64 * 33];

    const int tid = threadIdx.x;
    const int tx = tid & 15;         // m micro
    const int ty = tid >> 4;         // n micro
    const int b = blockIdx.z;
    const int nBase = blockIdx.y * 64;
    const int mBase = blockIdx.x * 64;

    const float* Ag = g_FQ + (size_t)(b * NQ + nBase) * KD;
    const float* Bg = g_FK + (size_t)(b * NK + mBase) * KD;

    float acc[4][4] = {};

    const int lr = tid >> 3;          // 0..31
    const int kq = (tid & 7) * 4;     // 0..28

    for (int k0 = 0; k0 < KD; k0 += 32) {
        __syncthreads();
        #pragma unroll
        for (int half = 0; half < 2; half++) {
            int r = lr + half * 32;
            float4 va = *reinterpret_cast<const float4*>(&Ag[(size_t)r * KD + k0 + kq]);
            float4 vb = *reinterpret_cast<const float4*>(&Bg[(size_t)r * KD + k0 + kq]);
            As[r * 33 + kq + 0] = va.x; As[r * 33 + kq + 1] = va.y;
            As[r * 33 + kq + 2] = va.z; As[r * 33 + kq + 3] = va.w;
            Bs[r * 33 + kq + 0] = vb.x; Bs[r * 33 + kq + 1] = vb.y;
            Bs[r * 33 + kq + 2] = vb.z; Bs[r * 33 + kq + 3] = vb.w;
        }
        __syncthreads();

        #pragma unroll
        for (int kk = 0; kk < 32; kk++) {
            float a0 = As[(ty * 4 + 0) * 33 + kk];
            float a1 = As[(ty * 4 + 1) * 33 + kk];
            float a2 = As[(ty * 4 + 2) * 33 + kk];
            float a3 = As[(ty * 4 + 3) * 33 + kk];
            float b0 = Bs[(tx * 4 + 0) * 33 + kk];
            float b1 = Bs[(tx * 4 + 1) * 33 + kk];
            float b2 = Bs[(tx * 4 + 2) * 33 + kk];
            float b3 = Bs[(tx * 4 + 3) * 33 + kk];
            acc[0][0] = fmaf(a0, b0, acc[0][0]);
            acc[0][1] = fmaf(a0, b1, acc[0][1]);
            acc[0][2] = fmaf(a0, b2, acc[0][2]);
            acc[0][3] = fmaf(a0, b3, acc[0][3]);
            acc[1][0] = fmaf(a1, b0, acc[1][0]);
            acc[1][1] = fmaf(a1, b1, acc[1][1]);
            acc[1][2] = fmaf(a1, b2, acc[1][2]);
            acc[1][3] = fmaf(a1, b3, acc[1][3]);
            acc[2][0] = fmaf(a2, b0, acc[2][0]);
            acc[2][1] = fmaf(a2, b1, acc[2][1]);
            acc[2][2] = fmaf(a2, b2, acc[2][2]);
            acc[2][3] = fmaf(a2, b3, acc[2][3]);
            acc[3][0] = fmaf(a3, b0, acc[3][0]);
            acc[3][1] = fmaf(a3, b1, acc[3][1]);
            acc[3][2] = fmaf(a3, b2, acc[3][2]);
            acc[3][3] = fmaf(a3, b3, acc[3][3]);
        }
    }

    #pragma unroll
    for (int i = 0; i < 4; i++) {
        int n = nBase + ty * 4 + i;
        #pragma unroll
        for (int j = 0; j < 4; j++) {
            int m = mBase + tx * 4 + j;
            float d = 0.5f * acc[i][j];
            d = fminf(fmaxf(d, 1e-6f), 1e6f);
            out[((size_t)b * NQ + n) * NK + m] = sqrtf(d);
        }
    }
}

// ---------------------------------------------------------------------------
extern "C" void kernel_launch(void* const* d_in, const int* in_sizes, int n_in,
                              void* d_out, int out_size)
{
    const float* Q  = (const float*)d_in[0];
    const float* K  = (const float*)d_in[1];
    const float* w1 = (const float*)d_in[2];
    const float* b1 = (const float*)d_in[3];
    const float* w2 = (const float*)d_in[4];
    const float* b2 = (const float*)d_in[5];
    float* out = (float*)d_out;

    kA<<<NROWS / 8, 256>>>(Q, K, w1, b1, w2, b2);
    kB<<<NROWS, 256>>>(Q, K);
    dim3 gc(NK / 64, NQ / 64, BATCH);
    kC<<<gc, 256>>>(out);
}